// round 6
// baseline (speedup 1.0000x reference)
#include <cuda_runtime.h>
#include <cstdint>

// Input order (metadata):
// 0 exposure_params [200] f32 | 1 vignetting_params [4,3,5] f32
// 2 color_params [200,8] f32  | 3 crf_params [4,3,4] f32
// 4 rgb_in [H,W,3] f32        | 5 pixel_coords [H,W,2] f32 (unused; reconstructed)
// 6 resolution_w i32 | 7 resolution_h i32 | 8 camera_idx i32 | 9 frame_idx i32

// Shared-memory folded parameter layout:
//  0..2  PX[3]   (= -2*cx)
//  3..5  PY[3]   (= -2*cy)
//  6..8  PC[3]   (= cx^2+cy^2)
//  9..11 A1[3]   (= a1*inv_norm2)
// 12..14 A2[3]   (= a2*inv^2)
// 15..17 A3[3]   (= a3*inv^3)
// 18..26 M[9]    (exposure-folded color matrix, row-major)
// 27..29 G[3]    (gamma)
// 30..32 C0[3]   (= q1+q3)
// 33..35 C1[3]   (= q2-q3)
// 36     crf_on

#define SP_PX 0
#define SP_PY 3
#define SP_PC 6
#define SP_A1 9
#define SP_A2 12
#define SP_A3 15
#define SP_M  18
#define SP_G  27
#define SP_C0 30
#define SP_C1 33
#define SP_ON 36

__device__ __forceinline__ float mufu_lg2(float x) {
    float r; asm("lg2.approx.f32 %0, %1;" : "=f"(r) : "f"(x)); return r;
}
__device__ __forceinline__ float mufu_ex2(float x) {
    float r; asm("ex2.approx.f32 %0, %1;" : "=f"(r) : "f"(x)); return r;
}

// Per-pixel pipeline. ty[ch] = y^2 + PY[ch]*y + PC[ch] is hoisted per-thread
// (y is constant across the thread's 8 pixels).
__device__ __forceinline__ void process_pixel(const float* __restrict__ sp,
                                              const float* __restrict__ ty,
                                              float x, bool crf_on,
                                              float& r0, float& r1, float& r2c) {
    float c0 = r0, c1 = r1, c2 = r2c;

    // vignetting: r2u = x^2 + PX*x + ty = fma(x, x+PX, ty)
    {
        const float r2 = fmaf(x, x + sp[SP_PX + 0], ty[0]);
        float h = fmaf(r2, sp[SP_A3 + 0], sp[SP_A2 + 0]);
        h = fmaf(r2, h, sp[SP_A1 + 0]);
        c0 = fmaf(c0, r2 * h, c0);
    }
    {
        const float r2 = fmaf(x, x + sp[SP_PX + 1], ty[1]);
        float h = fmaf(r2, sp[SP_A3 + 1], sp[SP_A2 + 1]);
        h = fmaf(r2, h, sp[SP_A1 + 1]);
        c1 = fmaf(c1, r2 * h, c1);
    }
    {
        const float r2 = fmaf(x, x + sp[SP_PX + 2], ty[2]);
        float h = fmaf(r2, sp[SP_A3 + 2], sp[SP_A2 + 2]);
        h = fmaf(r2, h, sp[SP_A1 + 2]);
        c2 = fmaf(c2, r2 * h, c2);
    }

    // 3x3 color matrix (exposure folded in)
    float o0 = fmaf(sp[SP_M + 0], c0, fmaf(sp[SP_M + 1], c1, sp[SP_M + 2] * c2));
    float o1 = fmaf(sp[SP_M + 3], c0, fmaf(sp[SP_M + 4], c1, sp[SP_M + 5] * c2));
    float o2 = fmaf(sp[SP_M + 6], c0, fmaf(sp[SP_M + 7], c1, sp[SP_M + 8] * c2));

    // CRF gamma + anchored perturbation (collapsed: pert = C0 + C1*y)
    if (crf_on) {
        {
            const float xc = __saturatef(o0);
            const float yv = mufu_ex2(sp[SP_G + 0] * mufu_lg2(xc)); // xc=0 -> 0, correct
            o0 = fmaf(yv * (1.0f - yv), fmaf(sp[SP_C1 + 0], yv, sp[SP_C0 + 0]), yv);
        }
        {
            const float xc = __saturatef(o1);
            const float yv = mufu_ex2(sp[SP_G + 1] * mufu_lg2(xc));
            o1 = fmaf(yv * (1.0f - yv), fmaf(sp[SP_C1 + 1], yv, sp[SP_C0 + 1]), yv);
        }
        {
            const float xc = __saturatef(o2);
            const float yv = mufu_ex2(sp[SP_G + 2] * mufu_lg2(xc));
            o2 = fmaf(yv * (1.0f - yv), fmaf(sp[SP_C1 + 2], yv, sp[SP_C0 + 2]), yv);
        }
    }

    r0 = o0; r1 = o1; r2c = o2;
}

__global__ void __launch_bounds__(256) ppisp_fused(
    const float* __restrict__ exposure,
    const float* __restrict__ vig,
    const float* __restrict__ color,
    const float* __restrict__ crf,
    const float* __restrict__ in,
    float* __restrict__ out,
    const int* __restrict__ rw,
    const int* __restrict__ rh,
    const int* __restrict__ cam,
    const int* __restrict__ frm,
    unsigned npix) {
    __shared__ float sp[40];
    __shared__ unsigned sW;

    // Per-block parameter fold (tables are tiny; L2-cached after the first wave).
    const unsigned t = threadIdx.x;
    if (t < 4) {
        const int f = frm[0];
        const int c = cam[0];
        const float Wf = (float)rw[0];
        const float Hf = (float)rh[0];
        if (t < 3) {
            const int ch = (int)t;
            const float norm2 = (0.5f * Wf) * (0.5f * Wf) + (0.5f * Hf) * (0.5f * Hf);
            const float inv = 1.0f / norm2;
            float PX = 0.f, PY = 0.f, PC = 0.f, A1 = 0.f, A2 = 0.f, A3 = 0.f;
            float G = 1.f, C0 = 0.f, C1 = 0.f;
            if (c >= 0) {
                const float* vp = vig + ((size_t)c * 3 + ch) * 5;
                const float cx = (0.5f + vp[0]) * Wf;
                const float cy = (0.5f + vp[1]) * Hf;
                PX = -2.0f * cx;
                PY = -2.0f * cy;
                PC = fmaf(cx, cx, cy * cy);
                A1 = vp[2] * inv;
                A2 = vp[3] * inv * inv;
                A3 = vp[4] * inv * inv * inv;
                const float* q = crf + ((size_t)c * 3 + ch) * 4;
                G  = expf(q[0]);
                C0 = q[1] + q[3];
                C1 = q[2] - q[3];
            }
            sp[SP_PX + ch] = PX;
            sp[SP_PY + ch] = PY;
            sp[SP_PC + ch] = PC;
            sp[SP_A1 + ch] = A1;
            sp[SP_A2 + ch] = A2;
            sp[SP_A3 + ch] = A3;
            sp[SP_G  + ch] = G;
            sp[SP_C0 + ch] = C0;
            sp[SP_C1 + ch] = C1;
        } else {
            // t == 3: color matrix + exposure + flags
            const float e = (f >= 0) ? expf(exposure[f]) : 1.0f;
            float M[9];
            if (f >= 0) {
                const float* p = color + (size_t)f * 8;
                M[0] = 1.0f + p[0]; M[1] = p[1];        M[2] = p[2];
                M[3] = p[3];        M[4] = 1.0f + p[4]; M[5] = p[5];
                M[6] = p[6];        M[7] = p[7];        M[8] = 1.0f;
            } else {
                M[0] = 1.f; M[1] = 0.f; M[2] = 0.f;
                M[3] = 0.f; M[4] = 1.f; M[5] = 0.f;
                M[6] = 0.f; M[7] = 0.f; M[8] = 1.f;
            }
#pragma unroll
            for (int i = 0; i < 9; i++) sp[SP_M + i] = M[i] * e;
            sp[SP_ON] = (c >= 0) ? 1.0f : 0.0f;
            sW = (unsigned)rw[0];
        }
    }
    __syncthreads();

    const unsigned gid = blockIdx.x * blockDim.x + threadIdx.x;
    const unsigned p0 = gid * 8u;
    if (p0 >= npix) return;

    const unsigned W = sW;
    const bool crf_on = (sp[SP_ON] > 0.5f);

    unsigned row = p0 / W;
    unsigned col = p0 - row * W;

    if (p0 + 7u < npix && col + 7u < W) {
        // fast path: all 8 pixels in one row (always when W % 8 == 0)
        const float4* in4 = reinterpret_cast<const float4*>(in);
        float4* out4 = reinterpret_cast<float4*>(out);
        const size_t base = (size_t)gid * 6u;
        float4 A = in4[base + 0];
        float4 B = in4[base + 1];
        float4 C = in4[base + 2];
        float4 D = in4[base + 3];
        float4 E = in4[base + 4];
        float4 F = in4[base + 5];

        const float y = (float)row + 0.5f;
        const float x0 = (float)col + 0.5f;

        // hoist per-row, per-channel constant: ty = y^2 + PY*y + PC
        float ty[3];
#pragma unroll
        for (int ch = 0; ch < 3; ch++)
            ty[ch] = fmaf(y, y + sp[SP_PY + ch], sp[SP_PC + ch]);

        process_pixel(sp, ty, x0 + 0.f, crf_on, A.x, A.y, A.z);
        process_pixel(sp, ty, x0 + 1.f, crf_on, A.w, B.x, B.y);
        process_pixel(sp, ty, x0 + 2.f, crf_on, B.z, B.w, C.x);
        process_pixel(sp, ty, x0 + 3.f, crf_on, C.y, C.z, C.w);
        process_pixel(sp, ty, x0 + 4.f, crf_on, D.x, D.y, D.z);
        process_pixel(sp, ty, x0 + 5.f, crf_on, D.w, E.x, E.y);
        process_pixel(sp, ty, x0 + 6.f, crf_on, E.z, E.w, F.x);
        process_pixel(sp, ty, x0 + 7.f, crf_on, F.y, F.z, F.w);

        __stcs(&out4[base + 0], A);
        __stcs(&out4[base + 1], B);
        __stcs(&out4[base + 2], C);
        __stcs(&out4[base + 3], D);
        __stcs(&out4[base + 4], E);
        __stcs(&out4[base + 5], F);
    } else {
        // generic scalar path (tail / row-wrap)
        unsigned rr = row, cc = col;
        const unsigned pend = (p0 + 8u < npix) ? (p0 + 8u) : npix;
        for (unsigned p = p0; p < pend; p++) {
            float r = in[(size_t)p * 3 + 0];
            float g = in[(size_t)p * 3 + 1];
            float b = in[(size_t)p * 3 + 2];
            const float yy = (float)rr + 0.5f;
            float ty[3];
#pragma unroll
            for (int ch = 0; ch < 3; ch++)
                ty[ch] = fmaf(yy, yy + sp[SP_PY + ch], sp[SP_PC + ch]);
            process_pixel(sp, ty, (float)cc + 0.5f, crf_on, r, g, b);
            out[(size_t)p * 3 + 0] = r;
            out[(size_t)p * 3 + 1] = g;
            out[(size_t)p * 3 + 2] = b;
            cc++;
            if (cc == W) { cc = 0u; rr++; }
        }
    }
}

extern "C" void kernel_launch(void* const* d_in, const int* in_sizes, int n_in,
                              void* d_out, int out_size) {
    const float* exposure = (const float*)d_in[0];
    const float* vig      = (const float*)d_in[1];
    const float* color    = (const float*)d_in[2];
    const float* crf      = (const float*)d_in[3];
    const float* rgb_in   = (const float*)d_in[4];
    // d_in[5] = pixel_coords, intentionally unused (reconstructed analytically)
    const int* rw  = (const int*)d_in[6];
    const int* rh  = (const int*)d_in[7];
    const int* cam = (const int*)d_in[8];
    const int* frm = (const int*)d_in[9];
    float* out = (float*)d_out;

    const unsigned npix = (unsigned)(in_sizes[4] / 3);
    const unsigned nthreads = (npix + 7u) / 8u;
    const unsigned blocks = (nthreads + 255u) / 256u;

    ppisp_fused<<<blocks, 256>>>(exposure, vig, color, crf, rgb_in, out,
                                 rw, rh, cam, frm, npix);
}

// round 7
// speedup vs baseline: 1.0925x; 1.0925x over previous
#include <cuda_runtime.h>
#include <cstdint>

// Input order (metadata):
// 0 exposure_params [200] f32 | 1 vignetting_params [4,3,5] f32
// 2 color_params [200,8] f32  | 3 crf_params [4,3,4] f32
// 4 rgb_in [H,W,3] f32        | 5 pixel_coords [H,W,2] f32 (unused; reconstructed)
// 6 resolution_w i32 | 7 resolution_h i32 | 8 camera_idx i32 | 9 frame_idx i32

// Folded parameter blob. Layout of p[]:
//  0..2  PX[3]  (= -2*cx)        3..5  PY[3] (= -2*cy)     6..8  PC[3] (= cx^2+cy^2)
//  9..11 A1[3]  (= a1*inv)      12..14 A2[3] (= a2*inv^2) 15..17 A3[3] (= a3*inv^3)
// 18..26 M[9]   exposure-folded color matrix (row-major)
// 27..29 G[3]   gamma           30..32 C0[3] (= q1+q3)    33..35 C1[3] (= q2-q3)
// 36     crf_on
struct Blob {
    float p[40];
    unsigned W;
    unsigned pad[3];
};

__device__ Blob g_stage;        // written by precompute kernel
__constant__ Blob c_blob;       // filled via D2D memcpy node; read as LDCU/UR in main

__global__ void ppisp_precompute(const float* __restrict__ exposure,
                                 const float* __restrict__ vig,
                                 const float* __restrict__ color,
                                 const float* __restrict__ crf,
                                 const int* __restrict__ rw,
                                 const int* __restrict__ rh,
                                 const int* __restrict__ cam,
                                 const int* __restrict__ frm) {
    if (threadIdx.x != 0 || blockIdx.x != 0) return;
    const int f = frm[0];
    const int c = cam[0];
    const float W = (float)rw[0];
    const float H = (float)rh[0];
    g_stage.W = (unsigned)rw[0];

    const float e = (f >= 0) ? expf(exposure[f]) : 1.0f;
    const float norm2 = (0.5f * W) * (0.5f * W) + (0.5f * H) * (0.5f * H);
    const float inv = 1.0f / norm2;

    for (int ch = 0; ch < 3; ch++) {
        float PX = 0.f, PY = 0.f, PC = 0.f, A1 = 0.f, A2 = 0.f, A3 = 0.f;
        float G = 1.f, C0 = 0.f, C1 = 0.f;
        if (c >= 0) {
            const float* vp = vig + ((size_t)c * 3 + ch) * 5;
            const float cx = (0.5f + vp[0]) * W;
            const float cy = (0.5f + vp[1]) * H;
            PX = -2.0f * cx;
            PY = -2.0f * cy;
            PC = fmaf(cx, cx, cy * cy);
            A1 = vp[2] * inv;
            A2 = vp[3] * inv * inv;
            A3 = vp[4] * inv * inv * inv;
            const float* q = crf + ((size_t)c * 3 + ch) * 4;
            G  = expf(q[0]);
            C0 = q[1] + q[3];
            C1 = q[2] - q[3];
        }
        g_stage.p[0 + ch]  = PX;
        g_stage.p[3 + ch]  = PY;
        g_stage.p[6 + ch]  = PC;
        g_stage.p[9 + ch]  = A1;
        g_stage.p[12 + ch] = A2;
        g_stage.p[15 + ch] = A3;
        g_stage.p[27 + ch] = G;
        g_stage.p[30 + ch] = C0;
        g_stage.p[33 + ch] = C1;
    }

    float M[9];
    if (f >= 0) {
        const float* p = color + (size_t)f * 8;
        M[0] = 1.0f + p[0]; M[1] = p[1];        M[2] = p[2];
        M[3] = p[3];        M[4] = 1.0f + p[4]; M[5] = p[5];
        M[6] = p[6];        M[7] = p[7];        M[8] = 1.0f;
    } else {
        M[0] = 1.f; M[1] = 0.f; M[2] = 0.f;
        M[3] = 0.f; M[4] = 1.f; M[5] = 0.f;
        M[6] = 0.f; M[7] = 0.f; M[8] = 1.f;
    }
    for (int i = 0; i < 9; i++) g_stage.p[18 + i] = M[i] * e;

    g_stage.p[36] = (c >= 0) ? 1.0f : 0.0f;
    g_stage.p[37] = 0.f; g_stage.p[38] = 0.f; g_stage.p[39] = 0.f;
}

__device__ __forceinline__ float mufu_lg2(float x) {
    float r; asm("lg2.approx.f32 %0, %1;" : "=f"(r) : "f"(x)); return r;
}
__device__ __forceinline__ float mufu_ex2(float x) {
    float r; asm("ex2.approx.f32 %0, %1;" : "=f"(r) : "f"(x)); return r;
}

#define CP(i) (c_blob.p[(i)])

// Per-pixel pipeline. ty[ch] = y^2 + PY*y + PC hoisted per thread (constant row).
// All CP() accesses are warp-uniform constant loads -> LDCU into URs, no vector regs.
__device__ __forceinline__ void process_pixel(const float* __restrict__ ty,
                                              float x, bool crf_on,
                                              float& r0, float& r1, float& r2c) {
    float c0 = r0, c1 = r1, c2 = r2c;

    // vignetting: r2 = x^2 + PX*x + ty ; vig = 1 + r2*(A1 + r2*(A2 + r2*A3))
    {
        const float r2 = fmaf(x, x + CP(0), ty[0]);
        float h = fmaf(r2, CP(15), CP(12));
        h = fmaf(r2, h, CP(9));
        c0 = fmaf(c0, r2 * h, c0);
    }
    {
        const float r2 = fmaf(x, x + CP(1), ty[1]);
        float h = fmaf(r2, CP(16), CP(13));
        h = fmaf(r2, h, CP(10));
        c1 = fmaf(c1, r2 * h, c1);
    }
    {
        const float r2 = fmaf(x, x + CP(2), ty[2]);
        float h = fmaf(r2, CP(17), CP(14));
        h = fmaf(r2, h, CP(11));
        c2 = fmaf(c2, r2 * h, c2);
    }

    // 3x3 color matrix (exposure folded in)
    float o0 = fmaf(CP(18), c0, fmaf(CP(19), c1, CP(20) * c2));
    float o1 = fmaf(CP(21), c0, fmaf(CP(22), c1, CP(23) * c2));
    float o2 = fmaf(CP(24), c0, fmaf(CP(25), c1, CP(26) * c2));

    // CRF gamma + anchored perturbation (pert collapsed to C0 + C1*y)
    if (crf_on) {
        {
            const float xc = __saturatef(o0);
            const float yv = mufu_ex2(CP(27) * mufu_lg2(xc)); // xc=0 -> -inf -> 0, correct
            o0 = fmaf(yv * (1.0f - yv), fmaf(CP(33), yv, CP(30)), yv);
        }
        {
            const float xc = __saturatef(o1);
            const float yv = mufu_ex2(CP(28) * mufu_lg2(xc));
            o1 = fmaf(yv * (1.0f - yv), fmaf(CP(34), yv, CP(31)), yv);
        }
        {
            const float xc = __saturatef(o2);
            const float yv = mufu_ex2(CP(29) * mufu_lg2(xc));
            o2 = fmaf(yv * (1.0f - yv), fmaf(CP(35), yv, CP(32)), yv);
        }
    }

    r0 = o0; r1 = o1; r2c = o2;
}

__global__ void __launch_bounds__(256) ppisp_main(const float* __restrict__ in,
                                                  float* __restrict__ out,
                                                  unsigned npix) {
    const unsigned gid = blockIdx.x * blockDim.x + threadIdx.x;
    const unsigned p0 = gid * 4u;
    if (p0 >= npix) return;

    const unsigned W = c_blob.W;
    const bool crf_on = (CP(36) > 0.5f);

    // one integer division per thread
    const unsigned row = p0 / W;
    const unsigned col = p0 - row * W;

    if (p0 + 3u < npix && col + 3u < W) {
        // fast path: 4 pixels in one row (always taken when W % 4 == 0)
        const float4* in4 = reinterpret_cast<const float4*>(in);
        float4* out4 = reinterpret_cast<float4*>(out);
        const size_t base = (size_t)gid * 3u;
        float4 A = in4[base + 0];
        float4 B = in4[base + 1];
        float4 C = in4[base + 2];

        const float y = (float)row + 0.5f;
        const float x0 = (float)col + 0.5f;

        float ty[3];
#pragma unroll
        for (int ch = 0; ch < 3; ch++)
            ty[ch] = fmaf(y, y + CP(3 + ch), CP(6 + ch));

        process_pixel(ty, x0 + 0.f, crf_on, A.x, A.y, A.z);
        process_pixel(ty, x0 + 1.f, crf_on, A.w, B.x, B.y);
        process_pixel(ty, x0 + 2.f, crf_on, B.z, B.w, C.x);
        process_pixel(ty, x0 + 3.f, crf_on, C.y, C.z, C.w);

        __stcs(&out4[base + 0], A);
        __stcs(&out4[base + 1], B);
        __stcs(&out4[base + 2], C);
    } else {
        // generic tail / row-wrap path
        unsigned rr = row, cc = col;
        const unsigned pend = (p0 + 4u < npix) ? (p0 + 4u) : npix;
        for (unsigned p = p0; p < pend; p++) {
            float r = in[(size_t)p * 3 + 0];
            float g = in[(size_t)p * 3 + 1];
            float b = in[(size_t)p * 3 + 2];
            const float yy = (float)rr + 0.5f;
            float ty[3];
#pragma unroll
            for (int ch = 0; ch < 3; ch++)
                ty[ch] = fmaf(yy, yy + CP(3 + ch), CP(6 + ch));
            process_pixel(ty, (float)cc + 0.5f, crf_on, r, g, b);
            out[(size_t)p * 3 + 0] = r;
            out[(size_t)p * 3 + 1] = g;
            out[(size_t)p * 3 + 2] = b;
            cc++;
            if (cc == W) { cc = 0u; rr++; }
        }
    }
}

extern "C" void kernel_launch(void* const* d_in, const int* in_sizes, int n_in,
                              void* d_out, int out_size) {
    const float* exposure = (const float*)d_in[0];
    const float* vig      = (const float*)d_in[1];
    const float* color    = (const float*)d_in[2];
    const float* crf      = (const float*)d_in[3];
    const float* rgb_in   = (const float*)d_in[4];
    // d_in[5] = pixel_coords, intentionally unused (reconstructed analytically)
    const int* rw  = (const int*)d_in[6];
    const int* rh  = (const int*)d_in[7];
    const int* cam = (const int*)d_in[8];
    const int* frm = (const int*)d_in[9];
    float* out = (float*)d_out;

    const unsigned npix = (unsigned)(in_sizes[4] / 3);

    // 1) fold params into the staging blob on device
    ppisp_precompute<<<1, 1>>>(exposure, vig, color, crf, rw, rh, cam, frm);

    // 2) D2D copy staging -> __constant__ (graph-capturable memcpy node)
    void* stage_ptr = nullptr;
    cudaGetSymbolAddress(&stage_ptr, g_stage);
    cudaMemcpyToSymbolAsync(c_blob, stage_ptr, sizeof(Blob), 0,
                            cudaMemcpyDeviceToDevice);

    // 3) hot kernel: params via LDCU/uniform-register path
    const unsigned nthreads = (npix + 3u) / 4u;
    const unsigned blocks = (nthreads + 255u) / 256u;
    ppisp_main<<<blocks, 256>>>(rgb_in, out, npix);
}